// round 1
// baseline (speedup 1.0000x reference)
#include <cuda_runtime.h>

// Triangle_39719857553609:
//   in : decompFE [32768, 2016] float32 (flat strict-lower-triangle, row-major tril order)
//   out: [32768, 64, 64] float32, symmetric, zero diagonal.
//
// Strategy: one CTA per batch element. Stage the 2016-float row in shared
// memory (read from DRAM exactly once), then emit all 4096 output floats as
// coalesced float4 stores. Memory-bound: ~264MB read + ~537MB write.

#define N_ATOMS 64
#define NC2     2016            // 64*63/2
#define MAT     (N_ATOMS * N_ATOMS)   // 4096
#define THREADS 256

__global__ __launch_bounds__(THREADS) void triangle_kernel(
    const float* __restrict__ in, float* __restrict__ out)
{
    __shared__ float s[NC2];

    const int b = blockIdx.x;

    // ---- Stage input row: 2016 floats = 504 float4 loads ----
    const float4* in4 = reinterpret_cast<const float4*>(in + (size_t)b * NC2);
    float4* s4 = reinterpret_cast<float4*>(s);
    #pragma unroll
    for (int t = threadIdx.x; t < NC2 / 4; t += THREADS)
        s4[t] = in4[t];
    __syncthreads();

    // ---- Emit 4096 outputs as 1024 float4 stores (4 per thread) ----
    float4* out4 = reinterpret_cast<float4*>(out + (size_t)b * MAT);

    #pragma unroll
    for (int q = 0; q < MAT / 4 / THREADS; q++) {
        const int e4 = threadIdx.x + q * THREADS;   // float4 index within matrix
        const int i  = e4 >> 4;                     // row (64 cols = 16 float4/row)
        const int j0 = (e4 & 15) << 2;              // starting col of this float4
        const int tri_i = (i * (i - 1)) >> 1;       // base of row i in tril order

        float4 v;
        float* vp = reinterpret_cast<float*>(&v);
        #pragma unroll
        for (int m = 0; m < 4; m++) {
            const int j = j0 + m;
            float val;
            if (j < i)       val = s[tri_i + j];                 // lower triangle
            else if (j > i)  val = s[((j * (j - 1)) >> 1) + i];  // mirrored upper
            else             val = 0.0f;                         // diagonal
            vp[m] = val;
        }
        out4[e4] = v;
    }
}

extern "C" void kernel_launch(void* const* d_in, const int* in_sizes, int n_in,
                              void* d_out, int out_size)
{
    const float* decompFE = (const float*)d_in[0];
    float* out = (float*)d_out;

    const int batch = in_sizes[0] / NC2;   // 32768
    triangle_kernel<<<batch, THREADS>>>(decompFE, out);
}